// round 7
// baseline (speedup 1.0000x reference)
#include <cuda_runtime.h>
#include <cmath>
#include <cstdint>

static constexpr int H = 512, W = 512, BATCH = 8;
static constexpr int NPIX = H * W;
static constexpr int NXi = BATCH * 3 * NPIX;          // 6,291,456
static constexpr int NFEAT = BATCH * 32 * NPIX;       // 67,108,864
static constexpr int MAXB = 11;                       // int(b) <= 10 always
static constexpr int RBLOCKS = 512;
static constexpr int UBLOCKS = 1024;

__device__ float g_x1[NFEAT];
__device__ float g_x2[NFEAT];
__device__ float g_x3[NFEAT];
__device__ float g_U[2 * 16384];      // winograd-transformed w2, w3
__device__ float g_U7[4096];          // winograd-transformed w7 (cout padded to 4)
__device__ float g_part[UBLOCKS];
__device__ float g_sum[MAXB + 2];
__device__ float g_n3;
__device__ int   g_b;

// ---------------------------------------------------------------------------
// Initial mean reduction + params
// ---------------------------------------------------------------------------
__global__ void reduce1_k(const float* __restrict__ x) {
    const float4* x4 = reinterpret_cast<const float4*>(x);
    const int n4 = NXi / 4;
    float s = 0.f;
    for (int i = blockIdx.x * 256 + threadIdx.x; i < n4; i += gridDim.x * 256) {
        float4 v = x4[i];
        s += (v.x + v.y) + (v.z + v.w);
    }
#pragma unroll
    for (int o = 16; o; o >>= 1) s += __shfl_xor_sync(0xffffffffu, s, o);
    __shared__ float ws[8];
    if ((threadIdx.x & 31) == 0) ws[threadIdx.x >> 5] = s;
    __syncthreads();
    if (threadIdx.x < 32) {
        s = (threadIdx.x < 8) ? ws[threadIdx.x] : 0.f;
#pragma unroll
        for (int o = 4; o; o >>= 1) s += __shfl_xor_sync(0xffffffffu, s, o);
        if (threadIdx.x == 0) g_part[blockIdx.x] = s;
    }
}

__global__ void reduce2_k() {
    float s = 0.f;
    for (int i = threadIdx.x; i < RBLOCKS; i += 256) s += g_part[i];
#pragma unroll
    for (int o = 16; o; o >>= 1) s += __shfl_xor_sync(0xffffffffu, s, o);
    __shared__ float ws[8];
    if ((threadIdx.x & 31) == 0) ws[threadIdx.x >> 5] = s;
    __syncthreads();
    if (threadIdx.x == 0) {
        float t = 0.f;
#pragma unroll
        for (int i = 0; i < 8; i++) t += ws[i];
        g_sum[0] = t;
    }
}

__global__ void params_k() {
    float m32 = g_sum[0] / (float)NXi;
    double xx1 = (double)m32;
    double s = xx1 * xx1;
    double n3 = -0.79 * s + 0.81 * xx1 + 1.4;
    double bf;
    if (xx1 < 0.1)       bf = -25.0 * xx1 + 10.0;
    else if (xx1 < 0.45) bf = 17.14 * s - 15.14 * xx1 + 10.0;
    else                 bf = 5.66 * s - 2.93 * xx1 + 7.2;
    g_n3 = (float)n3;
    int b = (int)bf;
    if (b > MAXB) b = MAXB;
    g_b = b;
}

// ---------------------------------------------------------------------------
// Winograd F(2x2,3x3) weight transform: U = G g G^T (proven).
// U[cin*512 + pos*32 + cout], pos = i*4 + c.  blocks: 0 -> w2, 1 -> w3.
// ---------------------------------------------------------------------------
__global__ void wino_wt_k(const float* __restrict__ w2,
                          const float* __restrict__ w3) {
    const float* w = blockIdx.x ? w3 : w2;
    float* U = g_U + blockIdx.x * 16384;
    int t = threadIdx.x;
    int cout = t >> 5, cin = t & 31;
    float g[9];
#pragma unroll
    for (int i = 0; i < 9; i++) g[i] = w[(cout * 32 + cin) * 9 + i];
    float T[4][3];
#pragma unroll
    for (int c = 0; c < 3; c++) {
        T[0][c] = g[c];
        T[1][c] = 0.5f * (g[c] + g[3 + c] + g[6 + c]);
        T[2][c] = 0.5f * (g[c] - g[3 + c] + g[6 + c]);
        T[3][c] = g[6 + c];
    }
#pragma unroll
    for (int i = 0; i < 4; i++) {
        float u0 = T[i][0];
        float u1 = 0.5f * (T[i][0] + T[i][1] + T[i][2]);
        float u2 = 0.5f * (T[i][0] - T[i][1] + T[i][2]);
        float u3 = T[i][2];
        U[cin * 512 + (i * 4 + 0) * 32 + cout] = u0;
        U[cin * 512 + (i * 4 + 1) * 32 + cout] = u1;
        U[cin * 512 + (i * 4 + 2) * 32 + cout] = u2;
        U[cin * 512 + (i * 4 + 3) * 32 + cout] = u3;
    }
}

// Weight transform for conv7: 3 couts (padded to 4) x 64 cins.
// U7[cin*64 + pos*4 + cout].
__global__ void wino_wt7_k(const float* __restrict__ w7) {
    int t = threadIdx.x;
    for (int i = t; i < 4096; i += 256) g_U7[i] = 0.f;
    __syncthreads();
    if (t >= 192) return;
    int cout = t >> 6, cin = t & 63;
    float g[9];
#pragma unroll
    for (int i = 0; i < 9; i++) g[i] = w7[(cout * 64 + cin) * 9 + i];
    float T[4][3];
#pragma unroll
    for (int c = 0; c < 3; c++) {
        T[0][c] = g[c];
        T[1][c] = 0.5f * (g[c] + g[3 + c] + g[6 + c]);
        T[2][c] = 0.5f * (g[c] - g[3 + c] + g[6 + c]);
        T[3][c] = g[6 + c];
    }
#pragma unroll
    for (int i = 0; i < 4; i++) {
        float u0 = T[i][0];
        float u1 = 0.5f * (T[i][0] + T[i][1] + T[i][2]);
        float u2 = 0.5f * (T[i][0] - T[i][1] + T[i][2]);
        float u3 = T[i][2];
        g_U7[cin * 64 + (i * 4 + 0) * 4 + cout] = u0;
        g_U7[cin * 64 + (i * 4 + 1) * 4 + cout] = u1;
        g_U7[cin * 64 + (i * 4 + 2) * 4 + cout] = u2;
        g_U7[cin * 64 + (i * 4 + 3) * 4 + cout] = u3;
    }
}

// ---------------------------------------------------------------------------
// Input-transform macro shared by wino kernels.
// Thread-constant identity: xt_tile(0..31), xt_i(0..3), xt_cl(0..1);
// handles local cins {xt_cl, xt_cl+2} of the phase's 4.
// V layout: [cl*512 + (i*4+col)*32 + tile], buffer 2048 floats.
// ---------------------------------------------------------------------------
#define XFORM_IDS()                                                          \
    const int xt_tile = t & 31;                                              \
    const int xt_i    = (t >> 5) & 3;                                        \
    const int xt_cl   = t >> 7;                                              \
    const int xt_txx  = xt_tile & 15, xt_tyy = xt_tile >> 4;                 \
    const int R1[4] = {0, 1, 2, 1}, R2[4] = {2, 2, 1, 3};                    \
    const float RS[4] = {-1.f, 1.f, -1.f, -1.f};                             \
    const int xr1 = (2 * xt_tyy + R1[xt_i]) * 36 + 2 * xt_txx;               \
    const int xr2 = (2 * xt_tyy + R2[xt_i]) * 36 + 2 * xt_txx;               \
    const float xsr = RS[xt_i];

#define XFORM4(g, vdst)                                                      \
    _Pragma("unroll")                                                        \
    for (int cc_ = 0; cc_ < 2; ++cc_) {                                      \
        const int cl_ = xt_cl + 2 * cc_;                                     \
        const float* base_ = raw + ((g) * 4 + cl_) * 216;                    \
        float2 p0_ = *reinterpret_cast<const float2*>(base_ + xr1);          \
        float2 p1_ = *reinterpret_cast<const float2*>(base_ + xr1 + 2);      \
        float2 q0_ = *reinterpret_cast<const float2*>(base_ + xr2);          \
        float2 q1_ = *reinterpret_cast<const float2*>(base_ + xr2 + 2);      \
        float z0 = fmaf(xsr, q0_.x, p0_.x);                                  \
        float z1 = fmaf(xsr, q0_.y, p0_.y);                                  \
        float z2 = fmaf(xsr, q1_.x, p1_.x);                                  \
        float z3 = fmaf(xsr, q1_.y, p1_.y);                                  \
        float* vb_ = (vdst) + cl_ * 512 + xt_i * 128 + xt_tile;              \
        vb_[0]  = z0 - z2;                                                   \
        vb_[32] = z1 + z2;                                                   \
        vb_[64] = z2 - z1;                                                   \
        vb_[96] = z1 - z3;                                                   \
    }

// ---------------------------------------------------------------------------
// Fused Winograd F(2x2,3x3) conv 32->32, bias+relu.  v3: 4 cins/phase.
// Block 256 thr; output tile 32x * 4y px = 32 wino tiles.
// GEMM thread: p=t>>4 (pos), cg=t&3 (8 couts), tg=(t>>2)&3 (8 tiles);
// 64 accs; per phase: 256 FMA, 16 LDS.128, 1 barrier.
// smem floats: U 16384 | raw 6912 | V 2*2048  = 27392 (109,568 B).
// ---------------------------------------------------------------------------
__global__ void __launch_bounds__(256, 2) wino_k(
    const float* __restrict__ in, int usel,
    const float* __restrict__ bg, float* __restrict__ out)
{
    extern __shared__ float sm[];
    float* Us  = sm;                  // 16384
    float* raw = sm + 16384;          // 32 * 216
    float* V   = sm + 23296;          // 2 * 2048
    float* Ms  = sm;                  // epilogue reuse

    const int t = threadIdx.x;
    const int x0 = blockIdx.x << 5, y0 = blockIdx.y << 2, bb = blockIdx.z;

    {
        const float4* Ug = reinterpret_cast<const float4*>(g_U + usel * 16384);
        float4* Ud = reinterpret_cast<float4*>(Us);
        for (int i = t; i < 4096; i += 256) Ud[i] = Ug[i];
    }
    const float* inb = in + (size_t)bb * 32 * NPIX;
    for (int i = t; i < 32 * 204; i += 256) {
        int cin = i / 204, rem = i - cin * 204;
        int r = rem / 34, c = rem - r * 34;
        int gy = y0 - 1 + r, gx = x0 - 1 + c;
        float v = 0.f;
        if ((unsigned)gy < (unsigned)H && (unsigned)gx < (unsigned)W)
            v = inb[(size_t)cin * NPIX + gy * W + gx];
        raw[cin * 216 + r * 36 + c] = v;
    }
    __syncthreads();

    XFORM_IDS();

    const int p  = t >> 4;
    const int cg = t & 3;
    const int tg = (t >> 2) & 3;

    float acc[8][8];
#pragma unroll
    for (int i = 0; i < 8; i++)
#pragma unroll
        for (int j = 0; j < 8; j++) acc[i][j] = 0.f;

#define RANK1(u0_, u1_, v0_, v1_) do {                                       \
        float ua[8] = {u0_.x, u0_.y, u0_.z, u0_.w, u1_.x, u1_.y, u1_.z, u1_.w}; \
        float va[8] = {v0_.x, v0_.y, v0_.z, v0_.w, v1_.x, v1_.y, v1_.z, v1_.w}; \
        _Pragma("unroll")                                                    \
        for (int i_ = 0; i_ < 8; i_++)                                       \
            _Pragma("unroll")                                                \
            for (int j_ = 0; j_ < 8; j_++)                                   \
                acc[i_][j_] = fmaf(va[i_], ua[j_], acc[i_][j_]);             \
    } while (0)

    XFORM4(0, V);
    __syncthreads();

#pragma unroll 1
    for (int g = 0; g < 8; ++g) {
        if (g < 7) XFORM4(g + 1, V + ((g + 1) & 1) * 2048);
        const float* vp = V + (g & 1) * 2048;
#pragma unroll
        for (int cc = 0; cc < 4; ++cc) {
            const float4* ub = reinterpret_cast<const float4*>(
                Us + (g * 4 + cc) * 512 + p * 32 + cg * 8);
            const float4* vb = reinterpret_cast<const float4*>(
                vp + cc * 512 + p * 32 + tg * 8);
            float4 u0 = ub[0], u1 = ub[1];
            float4 v0 = vb[0], v1 = vb[1];
            RANK1(u0, u1, v0, v1);
        }
        __syncthreads();
    }

    // epilogue: M -> smem (XOR swizzle) -> inverse AtMA
    {
        float* Msw = Ms + p * 1024;
#pragma unroll
        for (int i = 0; i < 8; ++i) {
            int tile = tg * 8 + i;
            int base = tile * 32 + ((cg * 8) ^ (tile & 24));
            *reinterpret_cast<float4*>(Msw + base) =
                make_float4(acc[i][0], acc[i][1], acc[i][2], acc[i][3]);
            *reinterpret_cast<float4*>(Msw + base + 4) =
                make_float4(acc[i][4], acc[i][5], acc[i][6], acc[i][7]);
        }
    }
    __syncthreads();

    {
        const int co = t & 31, tq = t >> 5;
        const float bv = __ldg(&bg[co]);
        float* plane = out + ((size_t)(bb * 32 + co)) * NPIX;
#pragma unroll
        for (int tt = 0; tt < 4; ++tt) {
            int tile = tq * 4 + tt;
            int widx = tile * 32 + (co ^ (tile & 24));
            float m[16];
#pragma unroll
            for (int q = 0; q < 16; ++q) m[q] = Ms[q * 1024 + widx];
            float P00 = m[0] + m[4] + m[8],  P01 = m[1] + m[5] + m[9];
            float P02 = m[2] + m[6] + m[10], P03 = m[3] + m[7] + m[11];
            float P10 = m[4] - m[8] - m[12], P11 = m[5] - m[9] - m[13];
            float P12 = m[6] - m[10] - m[14], P13 = m[7] - m[11] - m[15];
            float y00 = P00 + P01 + P02 + bv;
            float y01 = P01 - P02 - P03 + bv;
            float y10 = P10 + P11 + P12 + bv;
            float y11 = P11 - P12 - P13 + bv;
            int txx = tile & 15, tyy = tile >> 4;
            float* ob = plane + (size_t)(y0 + 2 * tyy) * W + x0 + 2 * txx;
            *reinterpret_cast<float2*>(ob) =
                make_float2(fmaxf(y00, 0.f), fmaxf(y01, 0.f));
            *reinterpret_cast<float2*>(ob + W) =
                make_float2(fmaxf(y10, 0.f), fmaxf(y11, 0.f));
        }
    }
#undef RANK1
}

// ---------------------------------------------------------------------------
// Winograd conv7: cin=64 (concat x1,x3), cout=3 (pad 4), 0.5*tanh epilogue.
// Block 256 thr; 32 tiles (32x * 4y px). 16 phases of 4 cins.
// GEMM thread: p=t>>4, tg=t&15 -> tiles {2tg, 2tg+1}, all 4 couts; 8 accs.
// smem floats: U7 4096 | raw 64*216=13824 | V 2*2048 = 22016 (88,064 B).
// ---------------------------------------------------------------------------
__global__ void __launch_bounds__(256, 2) wino7_k(
    const float* __restrict__ x1, const float* __restrict__ x3,
    const float* __restrict__ bg, float* __restrict__ out, int accumulate)
{
    extern __shared__ float sm[];
    float* Us  = sm;                  // 4096
    float* raw = sm + 4096;           // 64 * 216
    float* V   = sm + 17920;          // 2 * 2048
    float* Ms  = sm;                  // epilogue reuse (2112 <= 4096)

    const int t = threadIdx.x;
    const int x0 = blockIdx.x << 5, y0 = blockIdx.y << 2, bb = blockIdx.z;

    {
        const float4* Ug = reinterpret_cast<const float4*>(g_U7);
        float4* Ud = reinterpret_cast<float4*>(Us);
        for (int i = t; i < 1024; i += 256) Ud[i] = Ug[i];
    }
    for (int i = t; i < 64 * 204; i += 256) {
        int cin = i / 204, rem = i - cin * 204;
        int r = rem / 34, c = rem - r * 34;
        int gy = y0 - 1 + r, gx = x0 - 1 + c;
        float v = 0.f;
        if ((unsigned)gy < (unsigned)H && (unsigned)gx < (unsigned)W) {
            const float* ip = (cin < 32)
                ? x1 + ((size_t)(bb * 32 + cin)) * NPIX
                : x3 + ((size_t)(bb * 32 + cin - 32)) * NPIX;
            v = ip[gy * W + gx];
        }
        raw[cin * 216 + r * 36 + c] = v;
    }
    __syncthreads();

    XFORM_IDS();

    const int p  = t >> 4;
    const int tg = t & 15;

    float acc[2][4];
#pragma unroll
    for (int i = 0; i < 2; i++)
#pragma unroll
        for (int j = 0; j < 4; j++) acc[i][j] = 0.f;

    XFORM4(0, V);
    __syncthreads();

#pragma unroll 1
    for (int g = 0; g < 16; ++g) {
        if (g < 15) XFORM4(g + 1, V + ((g + 1) & 1) * 2048);
        const float* vp = V + (g & 1) * 2048;
#pragma unroll
        for (int cc = 0; cc < 4; ++cc) {
            float4 u = *reinterpret_cast<const float4*>(
                Us + (g * 4 + cc) * 64 + p * 4);
            float2 v = *reinterpret_cast<const float2*>(
                vp + cc * 512 + p * 32 + 2 * tg);
#pragma unroll
            for (int j = 0; j < 4; ++j) {
                float uj = (&u.x)[j];
                acc[0][j] = fmaf(v.x, uj, acc[0][j]);
                acc[1][j] = fmaf(v.y, uj, acc[1][j]);
            }
        }
        __syncthreads();
    }

    // epilogue: M -> smem -> inverse AtMA, 0.5*tanh(+bias), accumulate
    {
        float* Msw = Ms + p * 132;
#pragma unroll
        for (int tt = 0; tt < 2; ++tt) {
            int tile = 2 * tg + tt;
            *reinterpret_cast<float4*>(Msw + tile * 4) =
                make_float4(acc[tt][0], acc[tt][1], acc[tt][2], acc[tt][3]);
        }
    }
    __syncthreads();

    if (t < 128) {
        const int tile = t >> 2, co = t & 3;
        if (co < 3) {
            const float bv = __ldg(&bg[co]);
            float m[16];
#pragma unroll
            for (int q = 0; q < 16; ++q) m[q] = Ms[q * 132 + tile * 4 + co];
            float P00 = m[0] + m[4] + m[8],  P01 = m[1] + m[5] + m[9];
            float P02 = m[2] + m[6] + m[10], P03 = m[3] + m[7] + m[11];
            float P10 = m[4] - m[8] - m[12], P11 = m[5] - m[9] - m[13];
            float P12 = m[6] - m[10] - m[14], P13 = m[7] - m[11] - m[15];
            float y00 = 0.5f * tanhf(P00 + P01 + P02 + bv);
            float y01 = 0.5f * tanhf(P01 - P02 - P03 + bv);
            float y10 = 0.5f * tanhf(P10 + P11 + P12 + bv);
            float y11 = 0.5f * tanhf(P11 - P12 - P13 + bv);
            int txx = tile & 15, tyy = tile >> 4;
            float* ob = out + ((size_t)(bb * 3 + co)) * NPIX
                      + (size_t)(y0 + 2 * tyy) * W + x0 + 2 * txx;
            if (accumulate) {
                float2 r0 = *reinterpret_cast<float2*>(ob);
                float2 r1 = *reinterpret_cast<float2*>(ob + W);
                y00 += r0.x; y01 += r0.y; y10 += r1.x; y11 += r1.y;
            }
            *reinterpret_cast<float2*>(ob)     = make_float2(y00, y01);
            *reinterpret_cast<float2*>(ob + W) = make_float2(y10, y11);
        }
    }
}

// ---------------------------------------------------------------------------
// Direct 3x3 conv for conv1 (CIN=3), round-1 proven kernel.
// ---------------------------------------------------------------------------
template <int CIN>
__global__ void __launch_bounds__(256) conv3x3_k(
    const float* __restrict__ in, const float* __restrict__ wg,
    const float* __restrict__ bg, float* __restrict__ out, int transform)
{
    __shared__ float w_s[CIN * 9 * 32];
    __shared__ float tile[10 * 35];
    const int t  = threadIdx.x;
    const int tg = t >> 6;
    const int pt = t & 63;
    const int lx = (pt & 7) << 2;
    const int ly = pt >> 3;
    const int bx = blockIdx.x << 5;
    const int by = blockIdx.y << 3;
    const int bb = blockIdx.z;

    for (int i = t; i < CIN * 9 * 32; i += 256) {
        int cout = i & 31;
        int rem  = i >> 5;
        int cin  = rem / 9, tap = rem - cin * 9;
        w_s[i] = wg[(cout * CIN + cin) * 9 + tap];
    }

    float acc[8][4];
#pragma unroll
    for (int c = 0; c < 8; c++)
#pragma unroll
        for (int pp = 0; pp < 4; pp++) acc[c][pp] = 0.f;

    const float* inb = in + (size_t)bb * CIN * NPIX;

    for (int cin = 0; cin < CIN; ++cin) {
        __syncthreads();
        const float* ip = inb + (size_t)cin * NPIX;
        for (int i = t; i < 340; i += 256) {
            int r = i / 34, c = i - r * 34;
            int gy = by - 1 + r, gx = bx - 1 + c;
            float v = 0.f;
            if ((unsigned)gy < (unsigned)H && (unsigned)gx < (unsigned)W) {
                v = ip[gy * W + gx];
                if (transform) v = 1.0f - v;
            }
            tile[r * 35 + c] = v;
        }
        __syncthreads();
        const float* wb = &w_s[cin * 288 + tg * 8];
#pragma unroll
        for (int ky = 0; ky < 3; ++ky) {
            float iv[6];
#pragma unroll
            for (int jj = 0; jj < 6; ++jj) iv[jj] = tile[(ly + ky) * 35 + lx + jj];
#pragma unroll
            for (int kx = 0; kx < 3; ++kx) {
                const float* wv = wb + (ky * 3 + kx) * 32;
#pragma unroll
                for (int c = 0; c < 8; ++c) {
                    float wf = wv[c];
#pragma unroll
                    for (int pp = 0; pp < 4; ++pp)
                        acc[c][pp] = fmaf(iv[kx + pp], wf, acc[c][pp]);
                }
            }
        }
    }

    const int oy = by + ly, ox = bx + lx;
#pragma unroll
    for (int c = 0; c < 8; ++c) {
        int cout = tg * 8 + c;
        float bv = bg[cout];
        float4 o;
        o.x = fmaxf(acc[c][0] + bv, 0.f);
        o.y = fmaxf(acc[c][1] + bv, 0.f);
        o.z = fmaxf(acc[c][2] + bv, 0.f);
        o.w = fmaxf(acc[c][3] + bv, 0.f);
        *reinterpret_cast<float4*>(
            &out[((size_t)(bb * 32 + cout)) * NPIX + oy * W + ox]) = o;
    }
}

// ---------------------------------------------------------------------------
// Fused refinement update (round-4 proven).
// ---------------------------------------------------------------------------
__global__ void update_k(const float4* __restrict__ xin, float4* __restrict__ x,
                         const float4* __restrict__ xr, int it, int first)
{
    const bool active = it < g_b;
    if (!active && !first) return;
    float m  = g_sum[it] * (1.0f / (float)NXi);
    float cf = (0.63f - m) / (g_n3 - m);
    const int n4 = NXi / 4;
    float s = 0.f;
    for (int i = blockIdx.x * 512 + threadIdx.x; i < n4; i += gridDim.x * 512) {
        float4 xv = first ? xin[i] : x[i];
        if (active) {
            float4 rv = xr[i];
            xv.x += rv.x * (xv.x * xv.x - xv.x) * cf;
            xv.y += rv.y * (xv.y * xv.y - xv.y) * cf;
            xv.z += rv.z * (xv.z * xv.z - xv.z) * cf;
            xv.w += rv.w * (xv.w * xv.w - xv.w) * cf;
            x[i] = xv;
        } else {
            x[i] = xv;
        }
        s += (xv.x + xv.y) + (xv.z + xv.w);
    }
#pragma unroll
    for (int o = 16; o; o >>= 1) s += __shfl_xor_sync(0xffffffffu, s, o);
    __shared__ float ws[16];
    if ((threadIdx.x & 31) == 0) ws[threadIdx.x >> 5] = s;
    __syncthreads();
    if (threadIdx.x < 32) {
        s = (threadIdx.x < 16) ? ws[threadIdx.x] : 0.f;
#pragma unroll
        for (int o = 8; o; o >>= 1) s += __shfl_xor_sync(0xffffffffu, s, o);
        if (threadIdx.x == 0) g_part[blockIdx.x] = s;
    }
}

__global__ void finalize_k(int it) {
    if (it >= g_b) return;
    float s = 0.f;
    for (int i = threadIdx.x; i < UBLOCKS; i += 256) s += g_part[i];
#pragma unroll
    for (int o = 16; o; o >>= 1) s += __shfl_xor_sync(0xffffffffu, s, o);
    __shared__ float ws[8];
    if ((threadIdx.x & 31) == 0) ws[threadIdx.x >> 5] = s;
    __syncthreads();
    if (threadIdx.x == 0) {
        float t = 0.f;
#pragma unroll
        for (int i = 0; i < 8; i++) t += ws[i];
        g_sum[it + 1] = t;
    }
}

// ---------------------------------------------------------------------------
static constexpr int WINO_SMEM  = 27392 * 4;   // 109,568 B
static constexpr int WINO7_SMEM = 22016 * 4;   //  88,064 B

extern "C" void kernel_launch(void* const* d_in, const int* in_sizes, int n_in,
                              void* d_out, int out_size)
{
    const float* x  = (const float*)d_in[0];
    const float* w1 = (const float*)d_in[1];
    const float* b1 = (const float*)d_in[2];
    const float* w2 = (const float*)d_in[3];
    const float* b2 = (const float*)d_in[4];
    const float* w3 = (const float*)d_in[5];
    const float* b3 = (const float*)d_in[6];
    const float* w7 = (const float*)d_in[7];
    const float* b7 = (const float*)d_in[8];

    float* xo = (float*)d_out;      // final x
    float* xr = xo + NXi;           // x_r

    float *px1, *px2, *px3;
    cudaGetSymbolAddress((void**)&px1, g_x1);
    cudaGetSymbolAddress((void**)&px2, g_x2);
    cudaGetSymbolAddress((void**)&px3, g_x3);

    cudaFuncSetAttribute(wino_k, cudaFuncAttributeMaxDynamicSharedMemorySize,
                         WINO_SMEM);
    cudaFuncSetAttribute(wino7_k, cudaFuncAttributeMaxDynamicSharedMemorySize,
                         WINO7_SMEM);

    dim3 blk(256);
    dim3 cg1(16, 64, 8);       // conv1: 32x8 px tiles
    dim3 cgw(16, 128, 8);      // wino / wino7: 32x4 px tiles

    reduce1_k<<<RBLOCKS, blk>>>(x);
    reduce2_k<<<1, blk>>>();
    params_k<<<1, 1>>>();
    wino_wt_k<<<2, 1024>>>(w2, w3);
    wino_wt7_k<<<1, 256>>>(w7);

    for (int br = 0; br < 2; ++br) {
        conv3x3_k<3><<<cg1, blk>>>(x, w1, b1, px1, br);
        wino_k<<<cgw, blk, WINO_SMEM>>>(px1, 0, b2, px2);
        wino_k<<<cgw, blk, WINO_SMEM>>>(px2, 1, b3, px3);
        wino7_k<<<cgw, blk, WINO7_SMEM>>>(px1, px3, b7, xr, br);
    }

    for (int it = 0; it < MAXB; ++it) {
        update_k<<<UBLOCKS, 512>>>((const float4*)x, (float4*)xo,
                                   (const float4*)xr, it, it == 0 ? 1 : 0);
        finalize_k<<<1, blk>>>(it);
    }
}

// round 8
// speedup vs baseline: 1.3823x; 1.3823x over previous
#include <cuda_runtime.h>
#include <cmath>
#include <cstdint>

static constexpr int H = 512, W = 512, BATCH = 8;
static constexpr int NPIX = H * W;
static constexpr int NXi = BATCH * 3 * NPIX;          // 6,291,456
static constexpr int NFEAT = BATCH * 32 * NPIX;       // 67,108,864
static constexpr int MAXB = 10;                       // int(b) <= 10 always
static constexpr int RBLOCKS = 512;
static constexpr int UBLOCKS = 1024;

__device__ float g_x1[NFEAT];
__device__ float g_x2[NFEAT];
__device__ float g_x3[NFEAT];
__device__ float g_U[2 * 16384];      // winograd-transformed w2, w3
__device__ float g_part[UBLOCKS];
__device__ float g_sum[MAXB + 2];
__device__ float g_n3;
__device__ int   g_b;

// ---------------------------------------------------------------------------
// Initial mean reduction + params
// ---------------------------------------------------------------------------
__global__ void reduce1_k(const float* __restrict__ x) {
    const float4* x4 = reinterpret_cast<const float4*>(x);
    const int n4 = NXi / 4;
    float s = 0.f;
    for (int i = blockIdx.x * 256 + threadIdx.x; i < n4; i += gridDim.x * 256) {
        float4 v = x4[i];
        s += (v.x + v.y) + (v.z + v.w);
    }
#pragma unroll
    for (int o = 16; o; o >>= 1) s += __shfl_xor_sync(0xffffffffu, s, o);
    __shared__ float ws[8];
    if ((threadIdx.x & 31) == 0) ws[threadIdx.x >> 5] = s;
    __syncthreads();
    if (threadIdx.x < 32) {
        s = (threadIdx.x < 8) ? ws[threadIdx.x] : 0.f;
#pragma unroll
        for (int o = 4; o; o >>= 1) s += __shfl_xor_sync(0xffffffffu, s, o);
        if (threadIdx.x == 0) g_part[blockIdx.x] = s;
    }
}

__global__ void reduce2_k() {
    float s = 0.f;
    for (int i = threadIdx.x; i < RBLOCKS; i += 256) s += g_part[i];
#pragma unroll
    for (int o = 16; o; o >>= 1) s += __shfl_xor_sync(0xffffffffu, s, o);
    __shared__ float ws[8];
    if ((threadIdx.x & 31) == 0) ws[threadIdx.x >> 5] = s;
    __syncthreads();
    if (threadIdx.x == 0) {
        float t = 0.f;
#pragma unroll
        for (int i = 0; i < 8; i++) t += ws[i];
        g_sum[0] = t;
    }
}

__global__ void params_k() {
    float m32 = g_sum[0] / (float)NXi;
    double xx1 = (double)m32;
    double s = xx1 * xx1;
    double n3 = -0.79 * s + 0.81 * xx1 + 1.4;
    double bf;
    if (xx1 < 0.1)       bf = -25.0 * xx1 + 10.0;
    else if (xx1 < 0.45) bf = 17.14 * s - 15.14 * xx1 + 10.0;
    else                 bf = 5.66 * s - 2.93 * xx1 + 7.2;
    g_n3 = (float)n3;
    int b = (int)bf;
    if (b > MAXB) b = MAXB;
    g_b = b;
}

// ---------------------------------------------------------------------------
// Winograd F(2x2,3x3) weight transform: U = G g G^T (proven).
// U[cin*512 + pos*32 + cout], pos = i*4 + c.  blocks: 0 -> w2, 1 -> w3.
// ---------------------------------------------------------------------------
__global__ void wino_wt_k(const float* __restrict__ w2,
                          const float* __restrict__ w3) {
    const float* w = blockIdx.x ? w3 : w2;
    float* U = g_U + blockIdx.x * 16384;
    int t = threadIdx.x;
    int cout = t >> 5, cin = t & 31;
    float g[9];
#pragma unroll
    for (int i = 0; i < 9; i++) g[i] = w[(cout * 32 + cin) * 9 + i];
    float T[4][3];
#pragma unroll
    for (int c = 0; c < 3; c++) {
        T[0][c] = g[c];
        T[1][c] = 0.5f * (g[c] + g[3 + c] + g[6 + c]);
        T[2][c] = 0.5f * (g[c] - g[3 + c] + g[6 + c]);
        T[3][c] = g[6 + c];
    }
#pragma unroll
    for (int i = 0; i < 4; i++) {
        float u0 = T[i][0];
        float u1 = 0.5f * (T[i][0] + T[i][1] + T[i][2]);
        float u2 = 0.5f * (T[i][0] - T[i][1] + T[i][2]);
        float u3 = T[i][2];
        U[cin * 512 + (i * 4 + 0) * 32 + cout] = u0;
        U[cin * 512 + (i * 4 + 1) * 32 + cout] = u1;
        U[cin * 512 + (i * 4 + 2) * 32 + cout] = u2;
        U[cin * 512 + (i * 4 + 3) * 32 + cout] = u3;
    }
}

// ---------------------------------------------------------------------------
// Fused Winograd F(2x2,3x3) conv 32->32, bias+relu.  v5: 512 threads.
// Output tile 32x * 4y px = 32 wino tiles; 8 phases x 4 cins.
// XFORM thread (1 slot each): xt_tile(32) x xt_i(4) x xt_cl(4 cins).
// GEMM thread: p=t>>5 (pos), rem=t&31: cg=rem&7 (4 couts), tg=rem>>3
// (8 tiles); 32 accs; per phase 128 FMA, 12 LDS.128, 1 barrier.
// Epilogue exchange conflict-free (no swizzle; verified bank patterns).
// smem floats: U 16384 | raw 6912 | V 2*2048 = 27392 (109,568 B); Ms reuses U.
// ---------------------------------------------------------------------------
__global__ void __launch_bounds__(512, 2) wino_k(
    const float* __restrict__ in, int usel,
    const float* __restrict__ bg, float* __restrict__ out)
{
    extern __shared__ float sm[];
    float* Us  = sm;                  // 16384
    float* raw = sm + 16384;          // 32 * 216
    float* V   = sm + 23296;          // 2 * 2048
    float* Ms  = sm;                  // epilogue reuse

    const int t = threadIdx.x;
    const int x0 = blockIdx.x << 5, y0 = blockIdx.y << 2, bb = blockIdx.z;

    {
        const float4* Ug = reinterpret_cast<const float4*>(g_U + usel * 16384);
        float4* Ud = reinterpret_cast<float4*>(Us);
        for (int i = t; i < 4096; i += 512) Ud[i] = Ug[i];
    }
    const float* inb = in + (size_t)bb * 32 * NPIX;
    for (int i = t; i < 32 * 204; i += 512) {
        int cin = i / 204, rem = i - cin * 204;
        int r = rem / 34, c = rem - r * 34;
        int gy = y0 - 1 + r, gx = x0 - 1 + c;
        float v = 0.f;
        if ((unsigned)gy < (unsigned)H && (unsigned)gx < (unsigned)W)
            v = inb[(size_t)cin * NPIX + gy * W + gx];
        raw[cin * 216 + r * 36 + c] = v;
    }
    __syncthreads();

    // ---- transform identity: one slot per thread ----
    const int xt_tile = t & 31;
    const int xt_i    = (t >> 5) & 3;
    const int xt_cl   = t >> 7;                    // 0..3 (cin within phase)
    const int xt_txx  = xt_tile & 15, xt_tyy = xt_tile >> 4;
    const int R1[4] = {0, 1, 2, 1}, R2[4] = {2, 2, 1, 3};
    const float RS[4] = {-1.f, 1.f, -1.f, -1.f};
    const int xr1 = (2 * xt_tyy + R1[xt_i]) * 36 + 2 * xt_txx;
    const int xr2 = (2 * xt_tyy + R2[xt_i]) * 36 + 2 * xt_txx;
    const float xsr = RS[xt_i];

#define XFORM(g, vdst) do {                                                  \
        const float* base_ = raw + ((g) * 4 + xt_cl) * 216;                  \
        float2 p0_ = *reinterpret_cast<const float2*>(base_ + xr1);          \
        float2 p1_ = *reinterpret_cast<const float2*>(base_ + xr1 + 2);      \
        float2 q0_ = *reinterpret_cast<const float2*>(base_ + xr2);          \
        float2 q1_ = *reinterpret_cast<const float2*>(base_ + xr2 + 2);      \
        float z0 = fmaf(xsr, q0_.x, p0_.x);                                  \
        float z1 = fmaf(xsr, q0_.y, p0_.y);                                  \
        float z2 = fmaf(xsr, q1_.x, p1_.x);                                  \
        float z3 = fmaf(xsr, q1_.y, p1_.y);                                  \
        float* vb_ = (vdst) + xt_cl * 512 + xt_i * 128 + xt_tile;            \
        vb_[0]  = z0 - z2;                                                   \
        vb_[32] = z1 + z2;                                                   \
        vb_[64] = z2 - z1;                                                   \
        vb_[96] = z1 - z3;                                                   \
    } while (0)

    // ---- gemm identity ----
    const int p  = t >> 5;          // pos 0..15
    const int cg = t & 7;           // cout grp: couts [4cg, 4cg+3]
    const int tg = (t >> 3) & 3;    // tile grp: tiles [8tg, 8tg+7]

    float acc[8][4];
#pragma unroll
    for (int i = 0; i < 8; i++)
#pragma unroll
        for (int j = 0; j < 4; j++) acc[i][j] = 0.f;

    XFORM(0, V);
    __syncthreads();

#pragma unroll 1
    for (int g = 0; g < 8; ++g) {
        if (g < 7) XFORM(g + 1, V + ((g + 1) & 1) * 2048);
        const float* vp = V + (g & 1) * 2048;
#pragma unroll
        for (int cc = 0; cc < 4; ++cc) {
            float4 u = *reinterpret_cast<const float4*>(
                Us + (g * 4 + cc) * 512 + p * 32 + cg * 4);
            const float4* vb = reinterpret_cast<const float4*>(
                vp + cc * 512 + p * 32 + tg * 8);
            float4 v0 = vb[0], v1 = vb[1];
            float va[8] = {v0.x, v0.y, v0.z, v0.w, v1.x, v1.y, v1.z, v1.w};
#pragma unroll
            for (int i = 0; i < 8; i++) {
                acc[i][0] = fmaf(va[i], u.x, acc[i][0]);
                acc[i][1] = fmaf(va[i], u.y, acc[i][1]);
                acc[i][2] = fmaf(va[i], u.z, acc[i][2]);
                acc[i][3] = fmaf(va[i], u.w, acc[i][3]);
            }
        }
        __syncthreads();
    }

    // ---- epilogue: M -> smem (conflict-free) -> inverse AtMA ----
    {
        float* Msw = Ms + p * 1024;
#pragma unroll
        for (int i = 0; i < 8; ++i) {
            int tile = tg * 8 + i;
            *reinterpret_cast<float4*>(Msw + tile * 32 + cg * 4) =
                make_float4(acc[i][0], acc[i][1], acc[i][2], acc[i][3]);
        }
    }
    __syncthreads();

    {
        const int co = t & 31, tq = t >> 5;    // 2 tiles per thread
        const float bv = __ldg(&bg[co]);
        float* plane = out + ((size_t)(bb * 32 + co)) * NPIX;
#pragma unroll
        for (int tt = 0; tt < 2; ++tt) {
            int tile = tq * 2 + tt;
            int widx = tile * 32 + co;
            float m[16];
#pragma unroll
            for (int q = 0; q < 16; ++q) m[q] = Ms[q * 1024 + widx];
            float P00 = m[0] + m[4] + m[8],  P01 = m[1] + m[5] + m[9];
            float P02 = m[2] + m[6] + m[10], P03 = m[3] + m[7] + m[11];
            float P10 = m[4] - m[8] - m[12], P11 = m[5] - m[9] - m[13];
            float P12 = m[6] - m[10] - m[14], P13 = m[7] - m[11] - m[15];
            float y00 = P00 + P01 + P02 + bv;
            float y01 = P01 - P02 - P03 + bv;
            float y10 = P10 + P11 + P12 + bv;
            float y11 = P11 - P12 - P13 + bv;
            int txx = tile & 15, tyy = tile >> 4;
            float* ob = plane + (size_t)(y0 + 2 * tyy) * W + x0 + 2 * txx;
            *reinterpret_cast<float2*>(ob) =
                make_float2(fmaxf(y00, 0.f), fmaxf(y01, 0.f));
            *reinterpret_cast<float2*>(ob + W) =
                make_float2(fmaxf(y10, 0.f), fmaxf(y11, 0.f));
        }
    }
#undef XFORM
}

// ---------------------------------------------------------------------------
// Direct 3x3 conv for conv1 (CIN=3), round-1 proven kernel.
// ---------------------------------------------------------------------------
template <int CIN>
__global__ void __launch_bounds__(256) conv3x3_k(
    const float* __restrict__ in, const float* __restrict__ wg,
    const float* __restrict__ bg, float* __restrict__ out, int transform)
{
    __shared__ float w_s[CIN * 9 * 32];
    __shared__ float tile[10 * 35];
    const int t  = threadIdx.x;
    const int tg = t >> 6;
    const int pt = t & 63;
    const int lx = (pt & 7) << 2;
    const int ly = pt >> 3;
    const int bx = blockIdx.x << 5;
    const int by = blockIdx.y << 3;
    const int bb = blockIdx.z;

    for (int i = t; i < CIN * 9 * 32; i += 256) {
        int cout = i & 31;
        int rem  = i >> 5;
        int cin  = rem / 9, tap = rem - cin * 9;
        w_s[i] = wg[(cout * CIN + cin) * 9 + tap];
    }

    float acc[8][4];
#pragma unroll
    for (int c = 0; c < 8; c++)
#pragma unroll
        for (int pp = 0; pp < 4; pp++) acc[c][pp] = 0.f;

    const float* inb = in + (size_t)bb * CIN * NPIX;

    for (int cin = 0; cin < CIN; ++cin) {
        __syncthreads();
        const float* ip = inb + (size_t)cin * NPIX;
        for (int i = t; i < 340; i += 256) {
            int r = i / 34, c = i - r * 34;
            int gy = by - 1 + r, gx = bx - 1 + c;
            float v = 0.f;
            if ((unsigned)gy < (unsigned)H && (unsigned)gx < (unsigned)W) {
                v = ip[gy * W + gx];
                if (transform) v = 1.0f - v;
            }
            tile[r * 35 + c] = v;
        }
        __syncthreads();
        const float* wb = &w_s[cin * 288 + tg * 8];
#pragma unroll
        for (int ky = 0; ky < 3; ++ky) {
            float iv[6];
#pragma unroll
            for (int jj = 0; jj < 6; ++jj) iv[jj] = tile[(ly + ky) * 35 + lx + jj];
#pragma unroll
            for (int kx = 0; kx < 3; ++kx) {
                const float* wv = wb + (ky * 3 + kx) * 32;
#pragma unroll
                for (int c = 0; c < 8; ++c) {
                    float wf = wv[c];
#pragma unroll
                    for (int pp = 0; pp < 4; ++pp)
                        acc[c][pp] = fmaf(iv[kx + pp], wf, acc[c][pp]);
                }
            }
        }
    }

    const int oy = by + ly, ox = bx + lx;
#pragma unroll
    for (int c = 0; c < 8; ++c) {
        int cout = tg * 8 + c;
        float bv = bg[cout];
        float4 o;
        o.x = fmaxf(acc[c][0] + bv, 0.f);
        o.y = fmaxf(acc[c][1] + bv, 0.f);
        o.z = fmaxf(acc[c][2] + bv, 0.f);
        o.w = fmaxf(acc[c][3] + bv, 0.f);
        *reinterpret_cast<float4*>(
            &out[((size_t)(bb * 32 + cout)) * NPIX + oy * W + ox]) = o;
    }
}

// ---------------------------------------------------------------------------
// conv7 (cin=64 concat, cout=3, 0.5*tanh), round-1 proven kernel.
// ---------------------------------------------------------------------------
__global__ void __launch_bounds__(256) conv7_k(
    const float* __restrict__ x1, const float* __restrict__ x3,
    const float* __restrict__ wg, const float* __restrict__ bg,
    float* __restrict__ out, int accumulate)
{
    __shared__ float w_s[64 * 9 * 3];
    __shared__ float tile[34 * 35];
    const int t  = threadIdx.x;
    const int lx = (t & 7) << 2;
    const int ly = t >> 3;
    const int bx = blockIdx.x << 5;
    const int by = blockIdx.y << 5;
    const int bb = blockIdx.z;

    for (int i = t; i < 64 * 9 * 3; i += 256) {
        int cout = i % 3;
        int rem  = i / 3;
        int cin  = rem / 9, tap = rem - cin * 9;
        w_s[i] = wg[(cout * 64 + cin) * 9 + tap];
    }

    float acc[3][4];
#pragma unroll
    for (int c = 0; c < 3; c++)
#pragma unroll
        for (int pp = 0; pp < 4; pp++) acc[c][pp] = 0.f;

    for (int cin = 0; cin < 64; ++cin) {
        const float* ip = (cin < 32)
            ? x1 + ((size_t)(bb * 32 + cin)) * NPIX
            : x3 + ((size_t)(bb * 32 + cin - 32)) * NPIX;
        __syncthreads();
        for (int i = t; i < 34 * 34; i += 256) {
            int r = i / 34, c = i - r * 34;
            int gy = by - 1 + r, gx = bx - 1 + c;
            tile[r * 35 + c] =
                ((unsigned)gy < (unsigned)H && (unsigned)gx < (unsigned)W)
                    ? ip[gy * W + gx] : 0.f;
        }
        __syncthreads();
        const float* wb = &w_s[cin * 27];
#pragma unroll
        for (int ky = 0; ky < 3; ++ky) {
            float iv[6];
#pragma unroll
            for (int jj = 0; jj < 6; ++jj) iv[jj] = tile[(ly + ky) * 35 + lx + jj];
#pragma unroll
            for (int kx = 0; kx < 3; ++kx) {
                const float* wv = wb + (ky * 3 + kx) * 3;
#pragma unroll
                for (int c = 0; c < 3; ++c) {
                    float wf = wv[c];
#pragma unroll
                    for (int pp = 0; pp < 4; ++pp)
                        acc[c][pp] = fmaf(iv[kx + pp], wf, acc[c][pp]);
                }
            }
        }
    }

    const int oy = by + ly, ox = bx + lx;
#pragma unroll
    for (int c = 0; c < 3; ++c) {
        float bv = bg[c];
        float4 o;
        o.x = 0.5f * tanhf(acc[c][0] + bv);
        o.y = 0.5f * tanhf(acc[c][1] + bv);
        o.z = 0.5f * tanhf(acc[c][2] + bv);
        o.w = 0.5f * tanhf(acc[c][3] + bv);
        float4* op = reinterpret_cast<float4*>(
            &out[((size_t)(bb * 3 + c)) * NPIX + oy * W + ox]);
        if (accumulate) {
            float4 prev = *op;
            o.x += prev.x; o.y += prev.y; o.z += prev.z; o.w += prev.w;
        }
        *op = o;
    }
}

// ---------------------------------------------------------------------------
// Fused refinement update (round-4 proven).
// ---------------------------------------------------------------------------
__global__ void update_k(const float4* __restrict__ xin, float4* __restrict__ x,
                         const float4* __restrict__ xr, int it, int first)
{
    const bool active = it < g_b;
    if (!active && !first) return;
    float m  = g_sum[it] * (1.0f / (float)NXi);
    float cf = (0.63f - m) / (g_n3 - m);
    const int n4 = NXi / 4;
    float s = 0.f;
    for (int i = blockIdx.x * 512 + threadIdx.x; i < n4; i += gridDim.x * 512) {
        float4 xv = first ? xin[i] : x[i];
        if (active) {
            float4 rv = xr[i];
            xv.x += rv.x * (xv.x * xv.x - xv.x) * cf;
            xv.y += rv.y * (xv.y * xv.y - xv.y) * cf;
            xv.z += rv.z * (xv.z * xv.z - xv.z) * cf;
            xv.w += rv.w * (xv.w * xv.w - xv.w) * cf;
            x[i] = xv;
        } else {
            x[i] = xv;
        }
        s += (xv.x + xv.y) + (xv.z + xv.w);
    }
#pragma unroll
    for (int o = 16; o; o >>= 1) s += __shfl_xor_sync(0xffffffffu, s, o);
    __shared__ float ws[16];
    if ((threadIdx.x & 31) == 0) ws[threadIdx.x >> 5] = s;
    __syncthreads();
    if (threadIdx.x < 32) {
        s = (threadIdx.x < 16) ? ws[threadIdx.x] : 0.f;
#pragma unroll
        for (int o = 8; o; o >>= 1) s += __shfl_xor_sync(0xffffffffu, s, o);
        if (threadIdx.x == 0) g_part[blockIdx.x] = s;
    }
}

__global__ void finalize_k(int it) {
    if (it >= g_b) return;
    float s = 0.f;
    for (int i = threadIdx.x; i < UBLOCKS; i += 256) s += g_part[i];
#pragma unroll
    for (int o = 16; o; o >>= 1) s += __shfl_xor_sync(0xffffffffu, s, o);
    __shared__ float ws[8];
    if ((threadIdx.x & 31) == 0) ws[threadIdx.x >> 5] = s;
    __syncthreads();
    if (threadIdx.x == 0) {
        float t = 0.f;
#pragma unroll
        for (int i = 0; i < 8; i++) t += ws[i];
        g_sum[it + 1] = t;
    }
}

// ---------------------------------------------------------------------------
static constexpr int WINO_SMEM = 27392 * 4;   // 109,568 B

extern "C" void kernel_launch(void* const* d_in, const int* in_sizes, int n_in,
                              void* d_out, int out_size)
{
    const float* x  = (const float*)d_in[0];
    const float* w1 = (const float*)d_in[1];
    const float* b1 = (const float*)d_in[2];
    const float* w2 = (const float*)d_in[3];
    const float* b2 = (const float*)d_in[4];
    const float* w3 = (const float*)d_in[5];
    const float* b3 = (const float*)d_in[6];
    const float* w7 = (const float*)d_in[7];
    const float* b7 = (const float*)d_in[8];

    float* xo = (float*)d_out;      // final x
    float* xr = xo + NXi;           // x_r

    float *px1, *px2, *px3;
    cudaGetSymbolAddress((void**)&px1, g_x1);
    cudaGetSymbolAddress((void**)&px2, g_x2);
    cudaGetSymbolAddress((void**)&px3, g_x3);

    cudaFuncSetAttribute(wino_k, cudaFuncAttributeMaxDynamicSharedMemorySize,
                         WINO_SMEM);

    dim3 cg1(16, 64, 8);       // conv1: 32x8 px tiles, 256 thr
    dim3 cgw(16, 128, 8);      // wino: 32x4 px tiles, 512 thr
    dim3 cg7(16, 16, 8);       // conv7: 32x32 px tiles, 256 thr

    reduce1_k<<<RBLOCKS, 256>>>(x);
    reduce2_k<<<1, 256>>>();
    params_k<<<1, 1>>>();
    wino_wt_k<<<2, 1024>>>(w2, w3);

    for (int br = 0; br < 2; ++br) {
        conv3x3_k<3><<<cg1, 256>>>(x, w1, b1, px1, br);
        wino_k<<<cgw, 512, WINO_SMEM>>>(px1, 0, b2, px2);
        wino_k<<<cgw, 512, WINO_SMEM>>>(px2, 1, b3, px3);
        conv7_k<<<cg7, 256>>>(px1, px3, w7, b7, xr, br ? 2 : 0);
    }

    for (int it = 0; it < MAXB; ++it) {
        update_k<<<UBLOCKS, 512>>>((const float4*)x, (float4*)xo,
                                   (const float4*)xr, it, it == 0 ? 1 : 0);
        finalize_k<<<1, 256>>>(it);
    }
}

// round 9
// speedup vs baseline: 1.4981x; 1.0838x over previous
#include <cuda_runtime.h>
#include <cmath>
#include <cstdint>

static constexpr int H = 512, W = 512, BATCH = 8;
static constexpr int NPIX = H * W;
static constexpr int NXi = BATCH * 3 * NPIX;          // 6,291,456
static constexpr int NFEAT = BATCH * 32 * NPIX;       // 67,108,864
static constexpr int MAXB = 10;                       // int(b) <= 10 always
static constexpr int RBLOCKS = 512;
static constexpr int UBLOCKS = 1024;

__device__ float g_x1[NFEAT];
__device__ float g_x2[NFEAT];
__device__ float g_x3[NFEAT];
__device__ float g_U[2 * 16384];      // winograd-transformed w2, w3
__device__ float g_part[UBLOCKS];
__device__ float g_sum[MAXB + 2];
__device__ float g_n3;
__device__ int   g_b;

// ---------------------------------------------------------------------------
// Initial mean reduction + params
// ---------------------------------------------------------------------------
__global__ void reduce1_k(const float* __restrict__ x) {
    const float4* x4 = reinterpret_cast<const float4*>(x);
    const int n4 = NXi / 4;
    float s = 0.f;
    for (int i = blockIdx.x * 256 + threadIdx.x; i < n4; i += gridDim.x * 256) {
        float4 v = x4[i];
        s += (v.x + v.y) + (v.z + v.w);
    }
#pragma unroll
    for (int o = 16; o; o >>= 1) s += __shfl_xor_sync(0xffffffffu, s, o);
    __shared__ float ws[8];
    if ((threadIdx.x & 31) == 0) ws[threadIdx.x >> 5] = s;
    __syncthreads();
    if (threadIdx.x < 32) {
        s = (threadIdx.x < 8) ? ws[threadIdx.x] : 0.f;
#pragma unroll
        for (int o = 4; o; o >>= 1) s += __shfl_xor_sync(0xffffffffu, s, o);
        if (threadIdx.x == 0) g_part[blockIdx.x] = s;
    }
}

__global__ void reduce2_k() {
    float s = 0.f;
    for (int i = threadIdx.x; i < RBLOCKS; i += 256) s += g_part[i];
#pragma unroll
    for (int o = 16; o; o >>= 1) s += __shfl_xor_sync(0xffffffffu, s, o);
    __shared__ float ws[8];
    if ((threadIdx.x & 31) == 0) ws[threadIdx.x >> 5] = s;
    __syncthreads();
    if (threadIdx.x == 0) {
        float t = 0.f;
#pragma unroll
        for (int i = 0; i < 8; i++) t += ws[i];
        g_sum[0] = t;
    }
}

__global__ void params_k() {
    float m32 = g_sum[0] / (float)NXi;
    double xx1 = (double)m32;
    double s = xx1 * xx1;
    double n3 = -0.79 * s + 0.81 * xx1 + 1.4;
    double bf;
    if (xx1 < 0.1)       bf = -25.0 * xx1 + 10.0;
    else if (xx1 < 0.45) bf = 17.14 * s - 15.14 * xx1 + 10.0;
    else                 bf = 5.66 * s - 2.93 * xx1 + 7.2;
    g_n3 = (float)n3;
    int b = (int)bf;
    if (b > MAXB) b = MAXB;
    g_b = b;
}

// ---------------------------------------------------------------------------
// Winograd F(2x2,3x3) weight transform: U = G g G^T (proven).
// U[cin*512 + pos*32 + cout], pos = i*4 + c.  blocks: 0 -> w2, 1 -> w3.
// ---------------------------------------------------------------------------
__global__ void wino_wt_k(const float* __restrict__ w2,
                          const float* __restrict__ w3) {
    const float* w = blockIdx.x ? w3 : w2;
    float* U = g_U + blockIdx.x * 16384;
    int t = threadIdx.x;
    int cout = t >> 5, cin = t & 31;
    float g[9];
#pragma unroll
    for (int i = 0; i < 9; i++) g[i] = w[(cout * 32 + cin) * 9 + i];
    float T[4][3];
#pragma unroll
    for (int c = 0; c < 3; c++) {
        T[0][c] = g[c];
        T[1][c] = 0.5f * (g[c] + g[3 + c] + g[6 + c]);
        T[2][c] = 0.5f * (g[c] - g[3 + c] + g[6 + c]);
        T[3][c] = g[6 + c];
    }
#pragma unroll
    for (int i = 0; i < 4; i++) {
        float u0 = T[i][0];
        float u1 = 0.5f * (T[i][0] + T[i][1] + T[i][2]);
        float u2 = 0.5f * (T[i][0] - T[i][1] + T[i][2]);
        float u3 = T[i][2];
        U[cin * 512 + (i * 4 + 0) * 32 + cout] = u0;
        U[cin * 512 + (i * 4 + 1) * 32 + cout] = u1;
        U[cin * 512 + (i * 4 + 2) * 32 + cout] = u2;
        U[cin * 512 + (i * 4 + 3) * 32 + cout] = u3;
    }
}

// ---------------------------------------------------------------------------
// Fused Winograd F(2x2,3x3) conv 32->32, bias+relu.  v6: 512 threads,
// 4-tile loop per block (U staged ONCE per block -> gmem U traffic / 4).
// Per x-tile: 32x * 4y px = 32 wino tiles; 8 phases x 4 cins.
// XFORM thread (1 slot): xt_tile(32) x xt_i(4) x xt_cl(4 cins).
// GEMM thread: p=t>>5 (pos), cg=t&7 (4 couts), tg=(t>>3)&3 (8 tiles); 32 accs.
// Epilogue: two 16-tile halves through Msh (aliases raw/V; dead then).
// smem floats: U 16384 | raw 6912 | V 2*2048 = 27392 (109,568 B).
// ---------------------------------------------------------------------------
__global__ void __launch_bounds__(512, 2) wino_k(
    const float* __restrict__ in, int usel,
    const float* __restrict__ bg, float* __restrict__ out)
{
    extern __shared__ float sm[];
    float* Us  = sm;                  // 16384
    float* raw = sm + 16384;          // 32 * 216 = 6912
    float* V   = sm + 23296;          // 2 * 2048
    float* Msh = sm + 16384;          // epilogue half-buffer (8192), aliases raw+V[0:1280]

    const int t = threadIdx.x;
    const int y0 = blockIdx.y << 2, bb = blockIdx.z;

    // ---- stage U once per block ----
    {
        const float4* Ug = reinterpret_cast<const float4*>(g_U + usel * 16384);
        float4* Ud = reinterpret_cast<float4*>(Us);
        for (int i = t; i < 4096; i += 512) Ud[i] = Ug[i];
    }

    // ---- transform identity: one slot per thread ----
    const int xt_tile = t & 31;
    const int xt_i    = (t >> 5) & 3;
    const int xt_cl   = t >> 7;                    // 0..3 (cin within phase)
    const int xt_txx  = xt_tile & 15, xt_tyy = xt_tile >> 4;
    const int R1[4] = {0, 1, 2, 1}, R2[4] = {2, 2, 1, 3};
    const float RS[4] = {-1.f, 1.f, -1.f, -1.f};
    const int xr1 = (2 * xt_tyy + R1[xt_i]) * 36 + 2 * xt_txx;
    const int xr2 = (2 * xt_tyy + R2[xt_i]) * 36 + 2 * xt_txx;
    const float xsr = RS[xt_i];

#define XFORM(g, vdst) do {                                                  \
        const float* base_ = raw + ((g) * 4 + xt_cl) * 216;                  \
        float2 p0_ = *reinterpret_cast<const float2*>(base_ + xr1);          \
        float2 p1_ = *reinterpret_cast<const float2*>(base_ + xr1 + 2);      \
        float2 q0_ = *reinterpret_cast<const float2*>(base_ + xr2);          \
        float2 q1_ = *reinterpret_cast<const float2*>(base_ + xr2 + 2);      \
        float z0 = fmaf(xsr, q0_.x, p0_.x);                                  \
        float z1 = fmaf(xsr, q0_.y, p0_.y);                                  \
        float z2 = fmaf(xsr, q1_.x, p1_.x);                                  \
        float z3 = fmaf(xsr, q1_.y, p1_.y);                                  \
        float* vb_ = (vdst) + xt_cl * 512 + xt_i * 128 + xt_tile;            \
        vb_[0]  = z0 - z2;                                                   \
        vb_[32] = z1 + z2;                                                   \
        vb_[64] = z2 - z1;                                                   \
        vb_[96] = z1 - z3;                                                   \
    } while (0)

    // ---- gemm identity ----
    const int p  = t >> 5;          // pos 0..15
    const int cg = t & 7;           // cout grp: couts [4cg, 4cg+3]
    const int tg = (t >> 3) & 3;    // tile grp: tiles [8tg, 8tg+7]

    // ---- epilogue identity (constant across tiles) ----
    const int eco = t & 31, etl = t >> 5;       // cout, local tile
    const float bv = __ldg(&bg[eco]);
    float* plane = out + ((size_t)(bb * 32 + eco)) * NPIX;
    const float* inb = in + (size_t)bb * 32 * NPIX;

#pragma unroll 1
    for (int tix = 0; tix < 4; ++tix) {
        const int x0 = ((blockIdx.x << 2) + tix) << 5;

        // stage raw input: 32 cin x 6 rows x 34 cols (halo 1)
        for (int i = t; i < 32 * 204; i += 512) {
            int cin = i / 204, rem = i - cin * 204;
            int r = rem / 34, c = rem - r * 34;
            int gy = y0 - 1 + r, gx = x0 - 1 + c;
            float v = 0.f;
            if ((unsigned)gy < (unsigned)H && (unsigned)gx < (unsigned)W)
                v = inb[(size_t)cin * NPIX + gy * W + gx];
            raw[cin * 216 + r * 36 + c] = v;
        }
        __syncthreads();

        float acc[8][4];
#pragma unroll
        for (int i = 0; i < 8; i++)
#pragma unroll
            for (int j = 0; j < 4; j++) acc[i][j] = 0.f;

        XFORM(0, V);
        __syncthreads();

#pragma unroll 1
        for (int g = 0; g < 8; ++g) {
            if (g < 7) XFORM(g + 1, V + ((g + 1) & 1) * 2048);
            const float* vp = V + (g & 1) * 2048;
#pragma unroll
            for (int cc = 0; cc < 4; ++cc) {
                float4 u = *reinterpret_cast<const float4*>(
                    Us + (g * 4 + cc) * 512 + p * 32 + cg * 4);
                const float4* vb = reinterpret_cast<const float4*>(
                    vp + cc * 512 + p * 32 + tg * 8);
                float4 v0 = vb[0], v1 = vb[1];
                float va[8] = {v0.x, v0.y, v0.z, v0.w, v1.x, v1.y, v1.z, v1.w};
#pragma unroll
                for (int i = 0; i < 8; i++) {
                    acc[i][0] = fmaf(va[i], u.x, acc[i][0]);
                    acc[i][1] = fmaf(va[i], u.y, acc[i][1]);
                    acc[i][2] = fmaf(va[i], u.z, acc[i][2]);
                    acc[i][3] = fmaf(va[i], u.w, acc[i][3]);
                }
            }
            __syncthreads();
        }

        // ---- epilogue: two 16-tile halves through Msh ----
#pragma unroll
        for (int half = 0; half < 2; ++half) {
            if ((tg >> 1) == half) {
                float* Mw = Msh + p * 512 + (tg & 1) * 256 + cg * 4;
#pragma unroll
                for (int i = 0; i < 8; ++i)
                    *reinterpret_cast<float4*>(Mw + i * 32) =
                        make_float4(acc[i][0], acc[i][1], acc[i][2], acc[i][3]);
            }
            __syncthreads();
            {
                float m[16];
#pragma unroll
                for (int q = 0; q < 16; ++q)
                    m[q] = Msh[q * 512 + etl * 32 + eco];
                float P00 = m[0] + m[4] + m[8],  P01 = m[1] + m[5] + m[9];
                float P02 = m[2] + m[6] + m[10], P03 = m[3] + m[7] + m[11];
                float P10 = m[4] - m[8] - m[12], P11 = m[5] - m[9] - m[13];
                float P12 = m[6] - m[10] - m[14], P13 = m[7] - m[11] - m[15];
                float y00 = P00 + P01 + P02 + bv;
                float y01 = P01 - P02 - P03 + bv;
                float y10 = P10 + P11 + P12 + bv;
                float y11 = P11 - P12 - P13 + bv;
                float* ob = plane + (size_t)(y0 + 2 * half) * W + x0 + 2 * etl;
                *reinterpret_cast<float2*>(ob) =
                    make_float2(fmaxf(y00, 0.f), fmaxf(y01, 0.f));
                *reinterpret_cast<float2*>(ob + W) =
                    make_float2(fmaxf(y10, 0.f), fmaxf(y11, 0.f));
            }
            __syncthreads();
        }
    }
#undef XFORM
}

// ---------------------------------------------------------------------------
// Direct 3x3 conv for conv1 (CIN=3), round-1 proven kernel.
// ---------------------------------------------------------------------------
template <int CIN>
__global__ void __launch_bounds__(256) conv3x3_k(
    const float* __restrict__ in, const float* __restrict__ wg,
    const float* __restrict__ bg, float* __restrict__ out, int transform)
{
    __shared__ float w_s[CIN * 9 * 32];
    __shared__ float tile[10 * 35];
    const int t  = threadIdx.x;
    const int tg = t >> 6;
    const int pt = t & 63;
    const int lx = (pt & 7) << 2;
    const int ly = pt >> 3;
    const int bx = blockIdx.x << 5;
    const int by = blockIdx.y << 3;
    const int bb = blockIdx.z;

    for (int i = t; i < CIN * 9 * 32; i += 256) {
        int cout = i & 31;
        int rem  = i >> 5;
        int cin  = rem / 9, tap = rem - cin * 9;
        w_s[i] = wg[(cout * CIN + cin) * 9 + tap];
    }

    float acc[8][4];
#pragma unroll
    for (int c = 0; c < 8; c++)
#pragma unroll
        for (int pp = 0; pp < 4; pp++) acc[c][pp] = 0.f;

    const float* inb = in + (size_t)bb * CIN * NPIX;

    for (int cin = 0; cin < CIN; ++cin) {
        __syncthreads();
        const float* ip = inb + (size_t)cin * NPIX;
        for (int i = t; i < 340; i += 256) {
            int r = i / 34, c = i - r * 34;
            int gy = by - 1 + r, gx = bx - 1 + c;
            float v = 0.f;
            if ((unsigned)gy < (unsigned)H && (unsigned)gx < (unsigned)W) {
                v = ip[gy * W + gx];
                if (transform) v = 1.0f - v;
            }
            tile[r * 35 + c] = v;
        }
        __syncthreads();
        const float* wb = &w_s[cin * 288 + tg * 8];
#pragma unroll
        for (int ky = 0; ky < 3; ++ky) {
            float iv[6];
#pragma unroll
            for (int jj = 0; jj < 6; ++jj) iv[jj] = tile[(ly + ky) * 35 + lx + jj];
#pragma unroll
            for (int kx = 0; kx < 3; ++kx) {
                const float* wv = wb + (ky * 3 + kx) * 32;
#pragma unroll
                for (int c = 0; c < 8; ++c) {
                    float wf = wv[c];
#pragma unroll
                    for (int pp = 0; pp < 4; ++pp)
                        acc[c][pp] = fmaf(iv[kx + pp], wf, acc[c][pp]);
                }
            }
        }
    }

    const int oy = by + ly, ox = bx + lx;
#pragma unroll
    for (int c = 0; c < 8; ++c) {
        int cout = tg * 8 + c;
        float bv = bg[cout];
        float4 o;
        o.x = fmaxf(acc[c][0] + bv, 0.f);
        o.y = fmaxf(acc[c][1] + bv, 0.f);
        o.z = fmaxf(acc[c][2] + bv, 0.f);
        o.w = fmaxf(acc[c][3] + bv, 0.f);
        *reinterpret_cast<float4*>(
            &out[((size_t)(bb * 32 + cout)) * NPIX + oy * W + ox]) = o;
    }
}

// ---------------------------------------------------------------------------
// conv7 (cin=64 concat, cout=3, 0.5*tanh), round-1 proven kernel.
// ---------------------------------------------------------------------------
__global__ void __launch_bounds__(256) conv7_k(
    const float* __restrict__ x1, const float* __restrict__ x3,
    const float* __restrict__ wg, const float* __restrict__ bg,
    float* __restrict__ out, int accumulate)
{
    __shared__ float w_s[64 * 9 * 3];
    __shared__ float tile[34 * 35];
    const int t  = threadIdx.x;
    const int lx = (t & 7) << 2;
    const int ly = t >> 3;
    const int bx = blockIdx.x << 5;
    const int by = blockIdx.y << 5;
    const int bb = blockIdx.z;

    for (int i = t; i < 64 * 9 * 3; i += 256) {
        int cout = i % 3;
        int rem  = i / 3;
        int cin  = rem / 9, tap = rem - cin * 9;
        w_s[i] = wg[(cout * 64 + cin) * 9 + tap];
    }

    float acc[3][4];
#pragma unroll
    for (int c = 0; c < 3; c++)
#pragma unroll
        for (int pp = 0; pp < 4; pp++) acc[c][pp] = 0.f;

    for (int cin = 0; cin < 64; ++cin) {
        const float* ip = (cin < 32)
            ? x1 + ((size_t)(bb * 32 + cin)) * NPIX
            : x3 + ((size_t)(bb * 32 + cin - 32)) * NPIX;
        __syncthreads();
        for (int i = t; i < 34 * 34; i += 256) {
            int r = i / 34, c = i - r * 34;
            int gy = by - 1 + r, gx = bx - 1 + c;
            tile[r * 35 + c] =
                ((unsigned)gy < (unsigned)H && (unsigned)gx < (unsigned)W)
                    ? ip[gy * W + gx] : 0.f;
        }
        __syncthreads();
        const float* wb = &w_s[cin * 27];
#pragma unroll
        for (int ky = 0; ky < 3; ++ky) {
            float iv[6];
#pragma unroll
            for (int jj = 0; jj < 6; ++jj) iv[jj] = tile[(ly + ky) * 35 + lx + jj];
#pragma unroll
            for (int kx = 0; kx < 3; ++kx) {
                const float* wv = wb + (ky * 3 + kx) * 3;
#pragma unroll
                for (int c = 0; c < 3; ++c) {
                    float wf = wv[c];
#pragma unroll
                    for (int pp = 0; pp < 4; ++pp)
                        acc[c][pp] = fmaf(iv[kx + pp], wf, acc[c][pp]);
                }
            }
        }
    }

    const int oy = by + ly, ox = bx + lx;
#pragma unroll
    for (int c = 0; c < 3; ++c) {
        float bv = bg[c];
        float4 o;
        o.x = 0.5f * tanhf(acc[c][0] + bv);
        o.y = 0.5f * tanhf(acc[c][1] + bv);
        o.z = 0.5f * tanhf(acc[c][2] + bv);
        o.w = 0.5f * tanhf(acc[c][3] + bv);
        float4* op = reinterpret_cast<float4*>(
            &out[((size_t)(bb * 3 + c)) * NPIX + oy * W + ox]);
        if (accumulate) {
            float4 prev = *op;
            o.x += prev.x; o.y += prev.y; o.z += prev.z; o.w += prev.w;
        }
        *op = o;
    }
}

// ---------------------------------------------------------------------------
// Fused refinement update (round-4 proven).
// ---------------------------------------------------------------------------
__global__ void update_k(const float4* __restrict__ xin, float4* __restrict__ x,
                         const float4* __restrict__ xr, int it, int first)
{
    const bool active = it < g_b;
    if (!active && !first) return;
    float m  = g_sum[it] * (1.0f / (float)NXi);
    float cf = (0.63f - m) / (g_n3 - m);
    const int n4 = NXi / 4;
    float s = 0.f;
    for (int i = blockIdx.x * 512 + threadIdx.x; i < n4; i += gridDim.x * 512) {
        float4 xv = first ? xin[i] : x[i];
        if (active) {
            float4 rv = xr[i];
            xv.x += rv.x * (xv.x * xv.x - xv.x) * cf;
            xv.y += rv.y * (xv.y * xv.y - xv.y) * cf;
            xv.z += rv.z * (xv.z * xv.z - xv.z) * cf;
            xv.w += rv.w * (xv.w * xv.w - xv.w) * cf;
            x[i] = xv;
        } else {
            x[i] = xv;
        }
        s += (xv.x + xv.y) + (xv.z + xv.w);
    }
#pragma unroll
    for (int o = 16; o; o >>= 1) s += __shfl_xor_sync(0xffffffffu, s, o);
    __shared__ float ws[16];
    if ((threadIdx.x & 31) == 0) ws[threadIdx.x >> 5] = s;
    __syncthreads();
    if (threadIdx.x < 32) {
        s = (threadIdx.x < 16) ? ws[threadIdx.x] : 0.f;
#pragma unroll
        for (int o = 8; o; o >>= 1) s += __shfl_xor_sync(0xffffffffu, s, o);
        if (threadIdx.x == 0) g_part[blockIdx.x] = s;
    }
}

__global__ void finalize_k(int it) {
    if (it >= g_b) return;
    float s = 0.f;
    for (int i = threadIdx.x; i < UBLOCKS; i += 256) s += g_part[i];
#pragma unroll
    for (int o = 16; o; o >>= 1) s += __shfl_xor_sync(0xffffffffu, s, o);
    __shared__ float ws[8];
    if ((threadIdx.x & 31) == 0) ws[threadIdx.x >> 5] = s;
    __syncthreads();
    if (threadIdx.x == 0) {
        float t = 0.f;
#pragma unroll
        for (int i = 0; i < 8; i++) t += ws[i];
        g_sum[it + 1] = t;
    }
}

// ---------------------------------------------------------------------------
static constexpr int WINO_SMEM = 27392 * 4;   // 109,568 B

extern "C" void kernel_launch(void* const* d_in, const int* in_sizes, int n_in,
                              void* d_out, int out_size)
{
    const float* x  = (const float*)d_in[0];
    const float* w1 = (const float*)d_in[1];
    const float* b1 = (const float*)d_in[2];
    const float* w2 = (const float*)d_in[3];
    const float* b2 = (const float*)d_in[4];
    const float* w3 = (const float*)d_in[5];
    const float* b3 = (const float*)d_in[6];
    const float* w7 = (const float*)d_in[7];
    const float* b7 = (const float*)d_in[8];

    float* xo = (float*)d_out;      // final x
    float* xr = xo + NXi;           // x_r

    float *px1, *px2, *px3;
    cudaGetSymbolAddress((void**)&px1, g_x1);
    cudaGetSymbolAddress((void**)&px2, g_x2);
    cudaGetSymbolAddress((void**)&px3, g_x3);

    cudaFuncSetAttribute(wino_k, cudaFuncAttributeMaxDynamicSharedMemorySize,
                         WINO_SMEM);

    dim3 cg1(16, 64, 8);       // conv1: 32x8 px tiles, 256 thr
    dim3 cgw(4, 128, 8);       // wino: 4 x-tiles per block, 512 thr
    dim3 cg7(16, 16, 8);       // conv7: 32x32 px tiles, 256 thr

    // Order chosen so wino_k is the 4th launch (ncu capture slot).
    wino_wt_k<<<2, 1024>>>(w2, w3);                       // 1
    conv3x3_k<3><<<cg1, 256>>>(x, w1, b1, px1, 0);        // 2 (branch 0)
    reduce1_k<<<RBLOCKS, 256>>>(x);                       // 3
    wino_k<<<cgw, 512, WINO_SMEM>>>(px1, 0, b2, px2);     // 4  <- profiled
    wino_k<<<cgw, 512, WINO_SMEM>>>(px2, 1, b3, px3);     // 5
    conv7_k<<<cg7, 256>>>(px1, px3, w7, b7, xr, 0);       // 6
    reduce2_k<<<1, 256>>>();                              // 7
    params_k<<<1, 1>>>();                                 // 8

    // branch 1 (input 1-x)
    conv3x3_k<3><<<cg1, 256>>>(x, w1, b1, px1, 1);
    wino_k<<<cgw, 512, WINO_SMEM>>>(px1, 0, b2, px2);
    wino_k<<<cgw, 512, WINO_SMEM>>>(px2, 1, b3, px3);
    conv7_k<<<cg7, 256>>>(px1, px3, w7, b7, xr, 2);

    for (int it = 0; it < MAXB; ++it) {
        update_k<<<UBLOCKS, 512>>>((const float4*)x, (float4*)xo,
                                   (const float4*)xr, it, it == 0 ? 1 : 0);
        finalize_k<<<1, 256>>>(it);
    }
}